// round 10
// baseline (speedup 1.0000x reference)
#include <cuda_runtime.h>
#include <cuda_bf16.h>
#include <cstdint>

#define B_DIM 32
#define S_DIM 1024
#define H_DIM 1024
#define I_DIM 1024
#define KW    2048

// ---------------- scratch ----------------
__device__ float g_G[(size_t)3 * S_DIM * B_DIM * H_DIM];   // [g][t][b][h]
__device__ float g_hT[2][H_DIM * B_DIM];                   // h transposed [h][b]
__device__ unsigned g_flags[128 * 8];                      // 32B-strided arrive flags
__device__ __nv_bfloat16 g_xhi[(size_t)B_DIM * S_DIM * I_DIM];
__device__ __nv_bfloat16 g_xlo[(size_t)B_DIM * S_DIM * I_DIM];
__device__ __nv_bfloat16 g_whi[(size_t)3 * H_DIM * I_DIM]; // rows g*1024+h, k<1024
__device__ __nv_bfloat16 g_wlo[(size_t)3 * H_DIM * I_DIM];

// ---------------- helpers ----------------
__device__ __forceinline__ unsigned long long pack2(float lo, float hi) {
    unsigned long long r;
    asm("mov.b64 %0, {%1, %2};" : "=l"(r)
        : "r"(__float_as_uint(lo)), "r"(__float_as_uint(hi)));
    return r;
}
__device__ __forceinline__ unsigned long long ffma2(unsigned long long a,
                                                    unsigned long long b,
                                                    unsigned long long c) {
    unsigned long long d;
    asm("fma.rn.f32x2 %0, %1, %2, %3;" : "=l"(d) : "l"(a), "l"(b), "l"(c));
    return d;
}
__device__ __forceinline__ float2 unpack2(unsigned long long v) {
    unsigned lo, hi;
    asm("mov.b64 {%0, %1}, %2;" : "=r"(lo), "=r"(hi) : "l"(v));
    float2 f; f.x = __uint_as_float(lo); f.y = __uint_as_float(hi);
    return f;
}
__device__ __forceinline__ uint32_t smem_u32(const void* p) {
    uint32_t a;
    asm("{ .reg .u64 t; cvta.to.shared.u64 t, %1; cvt.u32.u64 %0, t; }"
        : "=r"(a) : "l"(p));
    return a;
}
__device__ __forceinline__ void cpasync16(uint32_t s, const void* g) {
    asm volatile("cp.async.cg.shared.global [%0], [%1], 16;" :: "r"(s), "l"(g));
}
#define CP_COMMIT() asm volatile("cp.async.commit_group;" ::: "memory")
#define CP_WAIT1()  asm volatile("cp.async.wait_group 1;" ::: "memory")
#define CP_WAIT0()  asm volatile("cp.async.wait_group 0;" ::: "memory")

__device__ __forceinline__ void ldsm_x4(uint32_t& r0, uint32_t& r1,
                                        uint32_t& r2, uint32_t& r3,
                                        uint32_t addr) {
    asm volatile("ldmatrix.sync.aligned.m8n8.x4.shared.b16 {%0,%1,%2,%3}, [%4];"
                 : "=r"(r0), "=r"(r1), "=r"(r2), "=r"(r3) : "r"(addr));
}
__device__ __forceinline__ void mma16816(float* d, const uint32_t* a,
                                         uint32_t b0, uint32_t b1) {
    asm volatile("mma.sync.aligned.m16n8k16.row.col.f32.bf16.bf16.f32 "
                 "{%0,%1,%2,%3}, {%4,%5,%6,%7}, {%8,%9}, {%0,%1,%2,%3};"
                 : "+f"(d[0]), "+f"(d[1]), "+f"(d[2]), "+f"(d[3])
                 : "r"(a[0]), "r"(a[1]), "r"(a[2]), "r"(a[3]),
                   "r"(b0), "r"(b1));
}

// ---------------- conversion kernels ----------------
__global__ void cvt_x(const float* __restrict__ x) {
    size_t i = (size_t)blockIdx.x * blockDim.x + threadIdx.x;
    if (i < (size_t)B_DIM * S_DIM * I_DIM) {
        float v = x[i];
        __nv_bfloat16 h = __float2bfloat16(v);
        g_xhi[i] = h;
        g_xlo[i] = __float2bfloat16(v - __bfloat162float(h));
    }
}
__global__ void cvt_w(const float* __restrict__ Wf, const float* __restrict__ Wo,
                      const float* __restrict__ Wc) {
    size_t i = (size_t)blockIdx.x * blockDim.x + threadIdx.x;
    if (i < (size_t)3 * H_DIM * I_DIM) {
        int g = (int)(i / (H_DIM * I_DIM));
        size_t rem = i - (size_t)g * H_DIM * I_DIM;
        int h = (int)(rem >> 10), k = (int)(rem & 1023);
        const float* W = (g == 0) ? Wf : (g == 1 ? Wo : Wc);
        float v = W[(size_t)h * KW + k];
        __nv_bfloat16 hh = __float2bfloat16(v);
        g_whi[i] = hh;
        g_wlo[i] = __float2bfloat16(v - __bfloat162float(hh));
    }
}

// ---------------- Phase 1: mma.sync bf16 GEMM (3-term hi/lo) ----------------
#define APAD 40
#define ALO_OFF 5120
#define BHI_OFF 10240
#define BLO_OFF 15360
#define STG_ELEMS 20480
#define GSMEM_BYTES (2 * STG_ELEMS * 2)

extern __shared__ __nv_bfloat16 g_sm[];

__global__ __launch_bounds__(256, 1)
void mma_gemm(const float* __restrict__ bf, const float* __restrict__ bo,
              const float* __restrict__ bc) {
    uint32_t sbase = smem_u32(g_sm);
    const int tid = threadIdx.x, lane = tid & 31, warp = tid >> 5;
    const int wm = warp & 1, wn = warp >> 1;
    const int g  = blockIdx.x >> 3;
    const int h0 = (blockIdx.x & 7) * 128;
    const int rowBase = blockIdx.y * 128;
    const size_t aG = (size_t)rowBase * 1024;
    const size_t bG = ((size_t)g * 1024 + h0) * 1024;

    auto loadStage = [&](int st, int kt) {
        uint32_t sb = sbase + st * (STG_ELEMS * 2);
        for (int i = tid; i < 512; i += 256) {
            int r = i >> 2, c = i & 3;
            uint32_t off = (uint32_t)(r * APAD + c * 8) * 2;
            size_t src = (size_t)r * 1024 + kt + c * 8;
            cpasync16(sb + off,               g_xhi + aG + src);
            cpasync16(sb + ALO_OFF * 2 + off, g_xlo + aG + src);
            cpasync16(sb + BHI_OFF * 2 + off, g_whi + bG + src);
            cpasync16(sb + BLO_OFF * 2 + off, g_wlo + bG + src);
        }
    };

    float acc[4][4][4];
#pragma unroll
    for (int mi = 0; mi < 4; mi++)
#pragma unroll
        for (int ni = 0; ni < 4; ni++)
#pragma unroll
            for (int u = 0; u < 4; u++) acc[mi][ni][u] = 0.f;

    loadStage(0, 0);  CP_COMMIT();
    loadStage(1, 32); CP_COMMIT();

    const int aRow = wm * 64 + (lane & 15);
    const int aColB = (lane >> 4) * 16;
    const int bRow = wn * 32 + (lane & 7) + ((lane >> 4) << 3);
    const int bColB = ((lane >> 3) & 1) * 16;

    for (int kt = 0; kt < 32; kt++) {
        CP_WAIT1();
        __syncthreads();
        uint32_t sb = sbase + (kt & 1) * (STG_ELEMS * 2);
#pragma unroll
        for (int kk = 0; kk < 2; kk++) {
            uint32_t ahi[4][4], alo[4][4];
#pragma unroll
            for (int mi = 0; mi < 4; mi++) {
                uint32_t ad = sb + (uint32_t)((aRow + mi * 16) * APAD) * 2
                            + kk * 32 + aColB;
                ldsm_x4(ahi[mi][0], ahi[mi][1], ahi[mi][2], ahi[mi][3], ad);
                ldsm_x4(alo[mi][0], alo[mi][1], alo[mi][2], alo[mi][3],
                        ad + ALO_OFF * 2);
            }
            uint32_t bhi[4][2], blo[4][2];
#pragma unroll
            for (int nh = 0; nh < 2; nh++) {
                uint32_t bd = sb + BHI_OFF * 2
                            + (uint32_t)((bRow + nh * 16) * APAD) * 2
                            + kk * 32 + bColB;
                uint32_t r0, r1, r2, r3;
                ldsm_x4(r0, r1, r2, r3, bd);
                bhi[nh * 2][0] = r0; bhi[nh * 2][1] = r1;
                bhi[nh * 2 + 1][0] = r2; bhi[nh * 2 + 1][1] = r3;
                ldsm_x4(r0, r1, r2, r3, bd + (BLO_OFF - BHI_OFF) * 2);
                blo[nh * 2][0] = r0; blo[nh * 2][1] = r1;
                blo[nh * 2 + 1][0] = r2; blo[nh * 2 + 1][1] = r3;
            }
#pragma unroll
            for (int mi = 0; mi < 4; mi++)
#pragma unroll
                for (int ni = 0; ni < 4; ni++) {
                    mma16816(acc[mi][ni], ahi[mi], bhi[ni][0], bhi[ni][1]);
                    mma16816(acc[mi][ni], ahi[mi], blo[ni][0], blo[ni][1]);
                    mma16816(acc[mi][ni], alo[mi], bhi[ni][0], bhi[ni][1]);
                }
        }
        __syncthreads();
        if (kt + 2 < 32) loadStage(kt & 1, (kt + 2) * 32);
        CP_COMMIT();
    }

    const float* bias = (g == 0) ? bf : (g == 1 ? bo : bc);
    const int b    = rowBase >> 10;
    const int tLoc = rowBase & 1023;
#pragma unroll
    for (int ni = 0; ni < 4; ni++) {
        int h = h0 + wn * 32 + ni * 8 + (lane & 3) * 2;
        float bx = __ldg(&bias[h]), by = __ldg(&bias[h + 1]);
#pragma unroll
        for (int mi = 0; mi < 4; mi++) {
            int t0 = tLoc + wm * 64 + mi * 16 + (lane >> 2);
            float2 v0 = make_float2(acc[mi][ni][0] + bx, acc[mi][ni][1] + by);
            float2 v1 = make_float2(acc[mi][ni][2] + bx, acc[mi][ni][3] + by);
            *(float2*)&g_G[(((size_t)g * S_DIM + t0) * B_DIM + b) * H_DIM + h] = v0;
            *(float2*)&g_G[(((size_t)g * S_DIM + t0 + 8) * B_DIM + b) * H_DIM + h] = v1;
        }
    }
}

// ---------------- init h0 (transposed) ----------------
__global__ void lstm_init_h(const float* __restrict__ h0) {
    int idx = blockIdx.x * blockDim.x + threadIdx.x;
    if (idx < B_DIM * H_DIM) {
        int b = idx >> 10, h = idx & 1023;
        g_hT[0][h * B_DIM + b] = h0[idx];
    }
}

// ---------------- Phase 2: persistent recurrence ----------------
#define NB_CTA 128
#define CPB    8
#define NTH    384
#define SMEM_FLOATS (24 * 1024 + 32768 + 256)
#define SMEM_BYTES (SMEM_FLOATS * 4)

__device__ __forceinline__ float sigm_f(float x) {
    return __fdividef(1.f, 1.f + __expf(-x));
}
__device__ __forceinline__ float tanh_f(float x) {
    return 1.f - __fdividef(2.f, 1.f + __expf(2.f * x));
}

extern __shared__ float s_mem[];

__global__ __launch_bounds__(NTH, 1)
void lstm_recurrent(const float* __restrict__ Wf, const float* __restrict__ Wo,
                    const float* __restrict__ Wc, const float* __restrict__ c0,
                    float* __restrict__ out, int out_size) {
    __shared__ unsigned s_base;
    float* ws   = s_mem;
    float* hbuf = s_mem + 24 * 1024;
    float* csm  = s_mem + 24 * 1024 + 32768;
    float* part = hbuf;                        // alias: [b]*801 + [p]*25 + gcol

    const int tid   = threadIdx.x;
    const int bid   = blockIdx.x;
    const int c0col = bid * CPB;
    const int lane  = tid & 31;
    const int warp  = tid >> 5;
    const int ks    = lane & 7;
    const int bg    = lane >> 3;
    const int rg    = warp % 3;
    const int kh    = warp / 3;

    if (tid == 0) s_base = g_flags[bid * 8];   // monotonic epoch base

    for (int idx = tid; idx < 24 * 256; idx += NTH) {
        int row = idx >> 8;
        int kq  = idx & 255;
        int gg = row >> 3, cc = row & 7;
        const float* Wsel = (gg == 0) ? Wf : (gg == 1 ? Wo : Wc);
        float4 v = *(const float4*)(Wsel + (size_t)(c0col + cc) * KW + I_DIM + kq * 4);
        *(float4*)&ws[row * 1024 + kq * 4] = v;
    }
    for (int idx = tid; idx < B_DIM * CPB; idx += NTH) {
        int cc = idx >> 5, bb = idx & 31;
        csm[cc * 32 + bb] = c0[bb * H_DIM + c0col + cc];
    }
    __syncthreads();
    const unsigned base = s_base;

    const float* wrowBase = ws + rg * 8 * 1024 + kh * 256 + ks * 4;
    const float* hBase    = hbuf + (kh * 256 + ks * 4) * 32;
    const uint32_t hbuf_a = smem_u32(hbuf);
    const int c0i = ((2 * bg) ^ ks) << 2;
    const int c1i = ((2 * bg + 1) ^ ks) << 2;
    const int p   = kh * 8 + ks;
    const bool wantTail = (out_size >= (B_DIM * S_DIM * H_DIM + 2 * B_DIM * H_DIM));

    for (int t = 0; t < S_DIM; t++) {
        const float* hsrc = g_hT[t & 1];
        float*       hdst = g_hT[(t + 1) & 1];

        // prefetch x-part (hidden under staging + dot)
        float gxr0 = 0.f, gxr1 = 0.f, gxr2 = 0.f;
        if (warp < 8) {
            size_t ofs = ((size_t)t * B_DIM + lane) * H_DIM + c0col + warp;
            const size_t GSTR = (size_t)S_DIM * B_DIM * H_DIM;
            gxr0 = __ldg(&g_G[ofs]);
            gxr1 = __ldg(&g_G[GSTR + ofs]);
            gxr2 = __ldg(&g_G[2 * GSTR + ofs]);
        }

        // stage h via cp.async (fire-and-forget, no exposed LDG->STS chain)
        for (int idx = tid; idx < 8192; idx += NTH) {
            int kk = idx >> 3, cc = idx & 7;
            uint32_t dst = hbuf_a
                + (uint32_t)(kk * 32 + ((cc ^ ((kk >> 2) & 7)) << 2)) * 4;
            cpasync16(dst, hsrc + (size_t)idx * 4);
        }
        CP_COMMIT();
        CP_WAIT0();
        __syncthreads();

        // dot: 8 rows x 8 batches, 4 consecutive k per slice, 8 j-iters
        unsigned long long acc[8][4];
#pragma unroll
        for (int r = 0; r < 8; r++)
#pragma unroll
            for (int q2 = 0; q2 < 4; q2++) acc[r][q2] = 0ull;

#pragma unroll
        for (int j = 0; j < 8; j++) {
            float4 wv[8];
#pragma unroll
            for (int r = 0; r < 8; r++)
                wv[r] = *(const float4*)(wrowBase + r * 1024 + j * 32);
            const float* hrow0 = hBase + j * 32 * 32;
#pragma unroll
            for (int dk = 0; dk < 4; dk++) {
                const float* hrow = hrow0 + dk * 32;
                longlong2 ha = *(const longlong2*)(hrow + c0i);
                longlong2 hb = *(const longlong2*)(hrow + c1i);
#pragma unroll
                for (int r = 0; r < 8; r++) {
                    float w = (dk == 0) ? wv[r].x : (dk == 1) ? wv[r].y
                            : (dk == 2) ? wv[r].z : wv[r].w;
                    unsigned long long wd = pack2(w, w);
                    acc[r][0] = ffma2(wd, (unsigned long long)ha.x, acc[r][0]);
                    acc[r][1] = ffma2(wd, (unsigned long long)ha.y, acc[r][1]);
                    acc[r][2] = ffma2(wd, (unsigned long long)hb.x, acc[r][2]);
                    acc[r][3] = ffma2(wd, (unsigned long long)hb.y, acc[r][3]);
                }
            }
        }
        __syncthreads();

#pragma unroll
        for (int r = 0; r < 8; r++) {
            int gcol = rg * 8 + r;
#pragma unroll
            for (int q2 = 0; q2 < 4; q2++) {
                float2 v = unpack2(acc[r][q2]);
                int b0 = bg * 8 + q2 * 2;
                part[b0 * 801 + p * 25 + gcol]       = v.x;
                part[(b0 + 1) * 801 + p * 25 + gcol] = v.y;
            }
        }
        __syncthreads();

        if (warp < 8) {
            const int cc = warp, bb = lane;
            const float* pb = &part[bb * 801];
            float s0a = 0.f, s0b = 0.f, s1a = 0.f, s1b = 0.f, s2a = 0.f, s2b = 0.f;
#pragma unroll
            for (int u = 0; u < 32; u += 2) {
                s0a += pb[u * 25 + cc];
                s0b += pb[(u + 1) * 25 + cc];
                s1a += pb[u * 25 + 8 + cc];
                s1b += pb[(u + 1) * 25 + 8 + cc];
                s2a += pb[u * 25 + 16 + cc];
                s2b += pb[(u + 1) * 25 + 16 + cc];
            }
            float pre0 = s0a + s0b + gxr0;
            float pre1 = s1a + s1b + gxr1;
            float pre2 = s2a + s2b + gxr2;

            float f  = sigm_f(pre0);
            float o  = sigm_f(pre1);
            float ch = tanh_f(pre2);
            float cold = csm[cc * 32 + bb];
            float cn = f * (cold - ch) + ch;
            float hn = o * tanh_f(cn);
            csm[cc * 32 + bb] = cn;

            int colg = c0col + cc;
            __stcg(&hdst[colg * B_DIM + bb], hn);
            out[((size_t)bb * S_DIM + t) * H_DIM + colg] = hn;
            if (t == S_DIM - 1 && wantTail) {
                size_t base2 = (size_t)B_DIM * S_DIM * H_DIM;
                out[base2 + (size_t)bb * H_DIM + colg] = hn;
                out[base2 + (size_t)B_DIM * H_DIM + (size_t)bb * H_DIM + colg] = cn;
            }
        }

        // ---- flag-array grid barrier (skip after final step) ----
        if (t < S_DIM - 1) {
            __syncthreads();
            const unsigned target = base + (unsigned)t + 1u;
            if (tid == 0) {
                __threadfence();
                asm volatile("st.global.release.gpu.b32 [%0], %1;"
                             :: "l"(&g_flags[bid * 8]), "r"(target) : "memory");
            }
            if (tid < 32) {
                unsigned f0, f1, f2, f3;
                bool ok;
                do {
                    asm volatile("ld.global.acquire.gpu.b32 %0, [%1];"
                                 : "=r"(f0) : "l"(&g_flags[tid * 8]));
                    asm volatile("ld.global.acquire.gpu.b32 %0, [%1];"
                                 : "=r"(f1) : "l"(&g_flags[(tid + 32) * 8]));
                    asm volatile("ld.global.acquire.gpu.b32 %0, [%1];"
                                 : "=r"(f2) : "l"(&g_flags[(tid + 64) * 8]));
                    asm volatile("ld.global.acquire.gpu.b32 %0, [%1];"
                                 : "=r"(f3) : "l"(&g_flags[(tid + 96) * 8]));
                    ok = ((int)(f0 - target) >= 0) & ((int)(f1 - target) >= 0)
                       & ((int)(f2 - target) >= 0) & ((int)(f3 - target) >= 0);
                    if (!__all_sync(0xFFFFFFFFu, ok)) { __nanosleep(20); ok = false; }
                } while (!ok);
            }
            __syncthreads();
        }
    }
}

// ---------------- launch ----------------
extern "C" void kernel_launch(void* const* d_in, const int* in_sizes, int n_in,
                              void* d_out, int out_size) {
    const float* x  = (const float*)d_in[0];
    const float* h0 = (const float*)d_in[1];
    const float* c0 = (const float*)d_in[2];
    const float* Wf = (const float*)d_in[3];
    const float* bf = (const float*)d_in[4];
    const float* Wo = (const float*)d_in[5];
    const float* bo = (const float*)d_in[6];
    const float* Wc = (const float*)d_in[7];
    const float* bc = (const float*)d_in[8];
    float* out = (float*)d_out;

    cudaFuncSetAttribute(mma_gemm,
                         cudaFuncAttributeMaxDynamicSharedMemorySize, GSMEM_BYTES);
    cudaFuncSetAttribute(lstm_recurrent,
                         cudaFuncAttributeMaxDynamicSharedMemorySize, SMEM_BYTES);

    cvt_x<<<(B_DIM * S_DIM * I_DIM + 255) / 256, 256>>>(x);
    cvt_w<<<(3 * H_DIM * I_DIM + 255) / 256, 256>>>(Wf, Wo, Wc);
    mma_gemm<<<dim3(24, 256), 256, GSMEM_BYTES>>>(bf, bo, bc);
    lstm_init_h<<<(B_DIM * H_DIM + 255) / 256, 256>>>(h0);
    lstm_recurrent<<<NB_CTA, NTH, SMEM_BYTES>>>(Wf, Wo, Wc, c0, out, out_size);
}

// round 11
// speedup vs baseline: 1.2193x; 1.2193x over previous
#include <cuda_runtime.h>
#include <cuda_bf16.h>
#include <cstdint>

#define B_DIM 32
#define S_DIM 1024
#define H_DIM 1024
#define I_DIM 1024
#define KW    2048

// ---------------- scratch ----------------
__device__ float g_G[(size_t)3 * S_DIM * B_DIM * H_DIM];   // [g][t][b][h]
__device__ __nv_bfloat16 g_hbhi[2][B_DIM * H_DIM];         // h bf16 hi, [b][h]
__device__ __nv_bfloat16 g_hblo[2][B_DIM * H_DIM];         // h bf16 lo, [b][h]
__device__ unsigned g_barCount = 0;
__device__ unsigned g_barGen   = 0;
__device__ __nv_bfloat16 g_xhi[(size_t)B_DIM * S_DIM * I_DIM];
__device__ __nv_bfloat16 g_xlo[(size_t)B_DIM * S_DIM * I_DIM];
__device__ __nv_bfloat16 g_whi[(size_t)3 * H_DIM * I_DIM]; // rows g*1024+h, k<1024
__device__ __nv_bfloat16 g_wlo[(size_t)3 * H_DIM * I_DIM];

// ---------------- helpers ----------------
__device__ __forceinline__ uint32_t smem_u32(const void* p) {
    uint32_t a;
    asm("{ .reg .u64 t; cvta.to.shared.u64 t, %1; cvt.u32.u64 %0, t; }"
        : "=r"(a) : "l"(p));
    return a;
}
__device__ __forceinline__ void cpasync16(uint32_t s, const void* g) {
    asm volatile("cp.async.cg.shared.global [%0], [%1], 16;" :: "r"(s), "l"(g));
}
#define CP_COMMIT() asm volatile("cp.async.commit_group;" ::: "memory")
#define CP_WAIT1()  asm volatile("cp.async.wait_group 1;" ::: "memory")

__device__ __forceinline__ void ldsm_x4(uint32_t& r0, uint32_t& r1,
                                        uint32_t& r2, uint32_t& r3,
                                        uint32_t addr) {
    asm volatile("ldmatrix.sync.aligned.m8n8.x4.shared.b16 {%0,%1,%2,%3}, [%4];"
                 : "=r"(r0), "=r"(r1), "=r"(r2), "=r"(r3) : "r"(addr));
}
__device__ __forceinline__ void mma16816(float* d, const uint32_t* a,
                                         uint32_t b0, uint32_t b1) {
    asm volatile("mma.sync.aligned.m16n8k16.row.col.f32.bf16.bf16.f32 "
                 "{%0,%1,%2,%3}, {%4,%5,%6,%7}, {%8,%9}, {%0,%1,%2,%3};"
                 : "+f"(d[0]), "+f"(d[1]), "+f"(d[2]), "+f"(d[3])
                 : "r"(a[0]), "r"(a[1]), "r"(a[2]), "r"(a[3]),
                   "r"(b0), "r"(b1));
}

// ---------------- conversion kernels ----------------
__global__ void cvt_x(const float* __restrict__ x) {
    size_t i = (size_t)blockIdx.x * blockDim.x + threadIdx.x;
    if (i < (size_t)B_DIM * S_DIM * I_DIM) {
        float v = x[i];
        __nv_bfloat16 h = __float2bfloat16(v);
        g_xhi[i] = h;
        g_xlo[i] = __float2bfloat16(v - __bfloat162float(h));
    }
}
__global__ void cvt_w(const float* __restrict__ Wf, const float* __restrict__ Wo,
                      const float* __restrict__ Wc) {
    size_t i = (size_t)blockIdx.x * blockDim.x + threadIdx.x;
    if (i < (size_t)3 * H_DIM * I_DIM) {
        int g = (int)(i / (H_DIM * I_DIM));
        size_t rem = i - (size_t)g * H_DIM * I_DIM;
        int h = (int)(rem >> 10), k = (int)(rem & 1023);
        const float* W = (g == 0) ? Wf : (g == 1 ? Wo : Wc);
        float v = W[(size_t)h * KW + k];
        __nv_bfloat16 hh = __float2bfloat16(v);
        g_whi[i] = hh;
        g_wlo[i] = __float2bfloat16(v - __bfloat162float(hh));
    }
}

// ---------------- Phase 1: mma.sync bf16 GEMM (3-term hi/lo), proven ----------------
#define APAD 40
#define ALO_OFF 5120
#define BHI_OFF 10240
#define BLO_OFF 15360
#define STG_ELEMS 20480
#define GSMEM_BYTES (2 * STG_ELEMS * 2)

extern __shared__ __nv_bfloat16 g_sm[];

__global__ __launch_bounds__(256, 1)
void mma_gemm(const float* __restrict__ bf, const float* __restrict__ bo,
              const float* __restrict__ bc) {
    uint32_t sbase = smem_u32(g_sm);
    const int tid = threadIdx.x, lane = tid & 31, warp = tid >> 5;
    const int wm = warp & 1, wn = warp >> 1;
    const int g  = blockIdx.x >> 3;
    const int h0 = (blockIdx.x & 7) * 128;
    const int rowBase = blockIdx.y * 128;
    const size_t aG = (size_t)rowBase * 1024;
    const size_t bG = ((size_t)g * 1024 + h0) * 1024;

    auto loadStage = [&](int st, int kt) {
        uint32_t sb = sbase + st * (STG_ELEMS * 2);
        for (int i = tid; i < 512; i += 256) {
            int r = i >> 2, c = i & 3;
            uint32_t off = (uint32_t)(r * APAD + c * 8) * 2;
            size_t src = (size_t)r * 1024 + kt + c * 8;
            cpasync16(sb + off,               g_xhi + aG + src);
            cpasync16(sb + ALO_OFF * 2 + off, g_xlo + aG + src);
            cpasync16(sb + BHI_OFF * 2 + off, g_whi + bG + src);
            cpasync16(sb + BLO_OFF * 2 + off, g_wlo + bG + src);
        }
    };

    float acc[4][4][4];
#pragma unroll
    for (int mi = 0; mi < 4; mi++)
#pragma unroll
        for (int ni = 0; ni < 4; ni++)
#pragma unroll
            for (int u = 0; u < 4; u++) acc[mi][ni][u] = 0.f;

    loadStage(0, 0);  CP_COMMIT();
    loadStage(1, 32); CP_COMMIT();

    const int aRow = wm * 64 + (lane & 15);
    const int aColB = (lane >> 4) * 16;
    const int bRow = wn * 32 + (lane & 7) + ((lane >> 4) << 3);
    const int bColB = ((lane >> 3) & 1) * 16;

    for (int kt = 0; kt < 32; kt++) {
        CP_WAIT1();
        __syncthreads();
        uint32_t sb = sbase + (kt & 1) * (STG_ELEMS * 2);
#pragma unroll
        for (int kk = 0; kk < 2; kk++) {
            uint32_t ahi[4][4], alo[4][4];
#pragma unroll
            for (int mi = 0; mi < 4; mi++) {
                uint32_t ad = sb + (uint32_t)((aRow + mi * 16) * APAD) * 2
                            + kk * 32 + aColB;
                ldsm_x4(ahi[mi][0], ahi[mi][1], ahi[mi][2], ahi[mi][3], ad);
                ldsm_x4(alo[mi][0], alo[mi][1], alo[mi][2], alo[mi][3],
                        ad + ALO_OFF * 2);
            }
            uint32_t bhi[4][2], blo[4][2];
#pragma unroll
            for (int nh = 0; nh < 2; nh++) {
                uint32_t bd = sb + BHI_OFF * 2
                            + (uint32_t)((bRow + nh * 16) * APAD) * 2
                            + kk * 32 + bColB;
                uint32_t r0, r1, r2, r3;
                ldsm_x4(r0, r1, r2, r3, bd);
                bhi[nh * 2][0] = r0; bhi[nh * 2][1] = r1;
                bhi[nh * 2 + 1][0] = r2; bhi[nh * 2 + 1][1] = r3;
                ldsm_x4(r0, r1, r2, r3, bd + (BLO_OFF - BHI_OFF) * 2);
                blo[nh * 2][0] = r0; blo[nh * 2][1] = r1;
                blo[nh * 2 + 1][0] = r2; blo[nh * 2 + 1][1] = r3;
            }
#pragma unroll
            for (int mi = 0; mi < 4; mi++)
#pragma unroll
                for (int ni = 0; ni < 4; ni++) {
                    mma16816(acc[mi][ni], ahi[mi], bhi[ni][0], bhi[ni][1]);
                    mma16816(acc[mi][ni], ahi[mi], blo[ni][0], blo[ni][1]);
                    mma16816(acc[mi][ni], alo[mi], bhi[ni][0], bhi[ni][1]);
                }
        }
        __syncthreads();
        if (kt + 2 < 32) loadStage(kt & 1, (kt + 2) * 32);
        CP_COMMIT();
    }

    const float* bias = (g == 0) ? bf : (g == 1 ? bo : bc);
    const int b    = rowBase >> 10;
    const int tLoc = rowBase & 1023;
#pragma unroll
    for (int ni = 0; ni < 4; ni++) {
        int h = h0 + wn * 32 + ni * 8 + (lane & 3) * 2;
        float bx = __ldg(&bias[h]), by = __ldg(&bias[h + 1]);
#pragma unroll
        for (int mi = 0; mi < 4; mi++) {
            int t0 = tLoc + wm * 64 + mi * 16 + (lane >> 2);
            float2 v0 = make_float2(acc[mi][ni][0] + bx, acc[mi][ni][1] + by);
            float2 v1 = make_float2(acc[mi][ni][2] + bx, acc[mi][ni][3] + by);
            *(float2*)&g_G[(((size_t)g * S_DIM + t0) * B_DIM + b) * H_DIM + h] = v0;
            *(float2*)&g_G[(((size_t)g * S_DIM + t0 + 8) * B_DIM + b) * H_DIM + h] = v1;
        }
    }
}

// ---------------- init h0 -> bf16 hi/lo [b][h] ----------------
__global__ void init_hb(const float* __restrict__ h0) {
    int i = blockIdx.x * blockDim.x + threadIdx.x;
    if (i < B_DIM * H_DIM) {
        float v = h0[i];
        __nv_bfloat16 hh = __float2bfloat16(v);
        g_hbhi[0][i] = hh;
        g_hblo[0][i] = __float2bfloat16(v - __bfloat162float(hh));
    }
}

// ---------------- Phase 2: persistent recurrence (tensor-core dot) ----------------
#define NB_CTA 128
#define CPB    8
#define NTH    256
// smem byte offsets
#define SW_HI   0u
#define SW_LO   66048u          // 32 rows * 2064 B
#define SH_HI   132096u
#define SH_LO   165376u         // SH_HI + 32*1040
#define PBUF_B  132096u         // alias over sH (dead during reduce)
#define CSM_B   198656u
#define TBUF_B  199680u
#define RSMEM_BYTES 200832u
#define WSTRB   2064            // sW row stride bytes (1032 bf16)
#define HSTRB   1040            // sH row stride bytes (520 bf16)
#define PSTR    34              // pbuf row stride floats

__device__ __forceinline__ void gridSync(unsigned nb) {
    __syncthreads();
    if (threadIdx.x == 0) {
        __threadfence();
        unsigned gen = *(volatile unsigned*)&g_barGen;
        if (atomicAdd(&g_barCount, 1u) == nb - 1u) {
            *(volatile unsigned*)&g_barCount = 0u;
            __threadfence();
            *(volatile unsigned*)&g_barGen = gen + 1u;
        } else {
            while (*(volatile unsigned*)&g_barGen == gen) { __nanosleep(20); }
        }
        __threadfence();
    }
    __syncthreads();
}
__device__ __forceinline__ float sigm_f(float x) {
    return __fdividef(1.f, 1.f + __expf(-x));
}
__device__ __forceinline__ float tanh_f(float x) {
    return 1.f - __fdividef(2.f, 1.f + __expf(2.f * x));
}

extern __shared__ char r_sm[];

__global__ __launch_bounds__(NTH, 1)
void lstm_recurrent(const float* __restrict__ Wf, const float* __restrict__ Wo,
                    const float* __restrict__ Wc, const float* __restrict__ c0,
                    float* __restrict__ out, int out_size) {
    const uint32_t sA = smem_u32(r_sm);
    float* csm  = (float*)(r_sm + CSM_B);     // [cc*32 + bb]
    float* tbuf = (float*)(r_sm + TBUF_B);    // [bb*9 + cc]
    float* pbuf = (float*)(r_sm + PBUF_B);    // [w][row(34)][batch]

    const int tid  = threadIdx.x;
    const int bid  = blockIdx.x;
    const int c0col = bid * CPB;
    const int lane = tid & 31;
    const int w    = tid >> 5;                // 8 warps, warp = K-slice owner
    const unsigned nb = gridDim.x;

    // ---- one-time: recurrent weights fp32 -> bf16 hi/lo into smem ----
    // rows 0..23 = gate*8+col, k = 0..1023 (W columns I..I+1023)
    for (int i = tid; i < 24 * 1024; i += NTH) {
        int row = i >> 10, k = i & 1023;
        int gg = row >> 3, cc = row & 7;
        const float* Wsel = (gg == 0) ? Wf : (gg == 1 ? Wo : Wc);
        float v = Wsel[(size_t)(c0col + cc) * KW + I_DIM + k];
        __nv_bfloat16 hh = __float2bfloat16(v);
        __nv_bfloat16 hl = __float2bfloat16(v - __bfloat162float(hh));
        *(__nv_bfloat16*)(r_sm + SW_HI + row * WSTRB + k * 2) = hh;
        *(__nv_bfloat16*)(r_sm + SW_LO + row * WSTRB + k * 2) = hl;
    }
    // rows 24..31 zero (read by ldmatrix, multiplied, discarded)
    for (int i = tid; i < 8 * (WSTRB / 4); i += NTH) {
        int row = 24 + i / (WSTRB / 4), wd = i % (WSTRB / 4);
        *(uint32_t*)(r_sm + SW_HI + row * WSTRB + wd * 4) = 0u;
        *(uint32_t*)(r_sm + SW_LO + row * WSTRB + wd * 4) = 0u;
    }
    for (int i = tid; i < B_DIM * CPB; i += NTH) {
        int cc = i >> 5, bb = i & 31;
        csm[cc * 32 + bb] = c0[bb * H_DIM + c0col + cc];
    }
    __syncthreads();

    const bool wantTail = (out_size >= (B_DIM * S_DIM * H_DIM + 2 * B_DIM * H_DIM));

    for (int t = 0; t < S_DIM; t++) {
        const int ep = t & 1, epn = ep ^ 1;

        // prefetch x-part pre-activations (warp -> cc, lane -> bb)
        float gxr0 = 0.f, gxr1 = 0.f, gxr2 = 0.f;
        {
            size_t ofs = ((size_t)t * B_DIM + lane) * H_DIM + c0col + w;
            const size_t GSTR = (size_t)S_DIM * B_DIM * H_DIM;
            gxr0 = __ldg(&g_G[ofs]);
            gxr1 = __ldg(&g_G[GSTR + ofs]);
            gxr2 = __ldg(&g_G[2 * GSTR + ofs]);
        }

        float acc[2][4][4];
#pragma unroll
        for (int mi = 0; mi < 2; mi++)
#pragma unroll
            for (int ni = 0; ni < 4; ni++)
#pragma unroll
                for (int u = 0; u < 4; u++) acc[mi][ni][u] = 0.f;

        // A-frag lane addressing (copied from mma_gemm, rows = gatecols)
        const int aRB = (lane & 15) * WSTRB + ((lane >> 4) << 4);
        // B-frag lane addressing (rows = batches)
        const int bRB = ((lane & 7) + ((lane >> 4) << 3)) * HSTRB
                      + (((lane >> 3) & 1) << 4);

#pragma unroll
        for (int hf = 0; hf < 2; hf++) {
            // stage h bf16 hi/lo for this K-half: 32 rows x 512 bf16 each
            for (int i = tid; i < 2048; i += NTH) {
                int row = i >> 6, c = i & 63;
                const size_t gsrc = (size_t)row * 1024 + hf * 512 + c * 8;
                float4 vh = __ldcg((const float4*)(g_hbhi[ep] + gsrc));
                *(float4*)(r_sm + SH_HI + row * HSTRB + c * 16) = vh;
                float4 vl = __ldcg((const float4*)(g_hblo[ep] + gsrc));
                *(float4*)(r_sm + SH_LO + row * HSTRB + c * 16) = vl;
            }
            __syncthreads();

#pragma unroll
            for (int kk = 0; kk < 4; kk++) {
                const uint32_t colWb = (uint32_t)(hf * 32 + w * 4 + kk) * 32;
                const uint32_t colHb = (uint32_t)(w * 4 + kk) * 32;
                uint32_t whi[2][4], wlo[2][4];
#pragma unroll
                for (int mi = 0; mi < 2; mi++) {
                    uint32_t ad = sA + SW_HI + (uint32_t)(mi * 16 * WSTRB)
                                + aRB + colWb;
                    ldsm_x4(whi[mi][0], whi[mi][1], whi[mi][2], whi[mi][3], ad);
                    ldsm_x4(wlo[mi][0], wlo[mi][1], wlo[mi][2], wlo[mi][3],
                            ad + (SW_LO - SW_HI));
                }
                uint32_t hhi[4][2], hlo[4][2];
#pragma unroll
                for (int nbk = 0; nbk < 2; nbk++) {
                    uint32_t bd = sA + SH_HI + (uint32_t)(nbk * 16 * HSTRB)
                                + bRB + colHb;
                    uint32_t r0, r1, r2, r3;
                    ldsm_x4(r0, r1, r2, r3, bd);
                    hhi[nbk * 2][0] = r0; hhi[nbk * 2][1] = r1;
                    hhi[nbk * 2 + 1][0] = r2; hhi[nbk * 2 + 1][1] = r3;
                    ldsm_x4(r0, r1, r2, r3, bd + (SH_LO - SH_HI));
                    hlo[nbk * 2][0] = r0; hlo[nbk * 2][1] = r1;
                    hlo[nbk * 2 + 1][0] = r2; hlo[nbk * 2 + 1][1] = r3;
                }
#pragma unroll
                for (int mi = 0; mi < 2; mi++)
#pragma unroll
                    for (int ni = 0; ni < 4; ni++)
                        mma16816(acc[mi][ni], whi[mi], hhi[ni][0], hhi[ni][1]);
#pragma unroll
                for (int mi = 0; mi < 2; mi++)
#pragma unroll
                    for (int ni = 0; ni < 4; ni++)
                        mma16816(acc[mi][ni], whi[mi], hlo[ni][0], hlo[ni][1]);
#pragma unroll
                for (int mi = 0; mi < 2; mi++)
#pragma unroll
                    for (int ni = 0; ni < 4; ni++)
                        mma16816(acc[mi][ni], wlo[mi], hhi[ni][0], hhi[ni][1]);
            }
            __syncthreads();   // sH reads done (before restage / pbuf alias)
        }

        // ---- partials to smem: pbuf[w][gatecol][batch] ----
#pragma unroll
        for (int mi = 0; mi < 2; mi++) {
            int row0 = mi * 16 + (lane >> 2);
#pragma unroll
            for (int ni = 0; ni < 4; ni++) {
                int col0 = ni * 8 + (lane & 3) * 2;
                float* pb = pbuf + w * (32 * PSTR);
                *(float2*)&pb[row0 * PSTR + col0] =
                    make_float2(acc[mi][ni][0], acc[mi][ni][1]);
                *(float2*)&pb[(row0 + 8) * PSTR + col0] =
                    make_float2(acc[mi][ni][2], acc[mi][ni][3]);
            }
        }
        __syncthreads();

        // ---- reduce 8 partials + gate math (warp = cc, lane = bb) ----
        {
            const int cc = w, bb = lane;
            float pre0 = gxr0, pre1 = gxr1, pre2 = gxr2;
#pragma unroll
            for (int u = 0; u < 8; u++) {
                const float* pb = pbuf + u * (32 * PSTR) + bb;
                pre0 += pb[(cc)      * PSTR];
                pre1 += pb[(8 + cc)  * PSTR];
                pre2 += pb[(16 + cc) * PSTR];
            }
            float f  = sigm_f(pre0);
            float o  = sigm_f(pre1);
            float ch = tanh_f(pre2);
            float cold = csm[cc * 32 + bb];
            float cn = f * (cold - ch) + ch;
            float hn = o * tanh_f(cn);
            csm[cc * 32 + bb] = cn;
            tbuf[bb * 9 + cc] = hn;

            int colg = c0col + cc;
            out[((size_t)bb * S_DIM + t) * H_DIM + colg] = hn;
            if (t == S_DIM - 1 && wantTail) {
                size_t base2 = (size_t)B_DIM * S_DIM * H_DIM;
                out[base2 + (size_t)bb * H_DIM + colg] = hn;
                out[base2 + (size_t)B_DIM * H_DIM + (size_t)bb * H_DIM + colg] = cn;
            }
        }
        __syncthreads();

        // ---- h -> bf16 hi/lo, coalesced store to next epoch ----
        {
            int bb = tid >> 3, cc = tid & 7;
            float v = tbuf[bb * 9 + cc];
            __nv_bfloat16 hh = __float2bfloat16(v);
            __nv_bfloat16 hl = __float2bfloat16(v - __bfloat162float(hh));
            unsigned short uh = *(unsigned short*)&hh;
            unsigned short ul = *(unsigned short*)&hl;
            size_t go = (size_t)bb * H_DIM + c0col + cc;
            asm volatile("st.global.cg.u16 [%0], %1;"
                         :: "l"(&g_hbhi[epn][go]), "h"(uh) : "memory");
            asm volatile("st.global.cg.u16 [%0], %1;"
                         :: "l"(&g_hblo[epn][go]), "h"(ul) : "memory");
        }

        if (t < S_DIM - 1) gridSync(nb);
    }
}

// ---------------- launch ----------------
extern "C" void kernel_launch(void* const* d_in, const int* in_sizes, int n_in,
                              void* d_out, int out_size) {
    const float* x  = (const float*)d_in[0];
    const float* h0 = (const float*)d_in[1];
    const float* c0 = (const float*)d_in[2];
    const float* Wf = (const float*)d_in[3];
    const float* bf = (const float*)d_in[4];
    const float* Wo = (const float*)d_in[5];
    const float* bo = (const float*)d_in[6];
    const float* Wc = (const float*)d_in[7];
    const float* bc = (const float*)d_in[8];
    float* out = (float*)d_out;

    cudaFuncSetAttribute(mma_gemm,
                         cudaFuncAttributeMaxDynamicSharedMemorySize, GSMEM_BYTES);
    cudaFuncSetAttribute(lstm_recurrent,
                         cudaFuncAttributeMaxDynamicSharedMemorySize, RSMEM_BYTES);

    cvt_x<<<(B_DIM * S_DIM * I_DIM + 255) / 256, 256>>>(x);
    cvt_w<<<(3 * H_DIM * I_DIM + 255) / 256, 256>>>(Wf, Wo, Wc);
    mma_gemm<<<dim3(24, 256), 256, GSMEM_BYTES>>>(bf, bo, bc);
    init_hb<<<(B_DIM * H_DIM + 255) / 256, 256>>>(h0);
    lstm_recurrent<<<NB_CTA, NTH, RSMEM_BYTES>>>(Wf, Wo, Wc, c0, out, out_size);
}

// round 13
// speedup vs baseline: 1.4478x; 1.1874x over previous
#include <cuda_runtime.h>
#include <cuda_bf16.h>
#include <cstdint>

#define B_DIM 32
#define S_DIM 1024
#define H_DIM 1024
#define I_DIM 1024
#define KW    2048

// ---------------- scratch ----------------
__device__ float g_G[(size_t)3 * S_DIM * B_DIM * H_DIM];   // [g][t][b][h]
__device__ __nv_bfloat16 g_hbhi[2][B_DIM * H_DIM];         // h bf16 hi, [b][h]
__device__ __nv_bfloat16 g_hblo[2][B_DIM * H_DIM];         // h bf16 lo, [b][h]
__device__ unsigned g_barCount = 0;
__device__ unsigned g_barGen   = 0;
__device__ __nv_bfloat16 g_xhi[(size_t)B_DIM * S_DIM * I_DIM];
__device__ __nv_bfloat16 g_xlo[(size_t)B_DIM * S_DIM * I_DIM];
__device__ __nv_bfloat16 g_whi[(size_t)3 * H_DIM * I_DIM]; // rows g*1024+h, k<1024
__device__ __nv_bfloat16 g_wlo[(size_t)3 * H_DIM * I_DIM];

// ---------------- helpers ----------------
__device__ __forceinline__ uint32_t smem_u32(const void* p) {
    uint32_t a;
    asm("{ .reg .u64 t; cvta.to.shared.u64 t, %1; cvt.u32.u64 %0, t; }"
        : "=r"(a) : "l"(p));
    return a;
}
__device__ __forceinline__ void cpasync16(uint32_t s, const void* g) {
    asm volatile("cp.async.cg.shared.global [%0], [%1], 16;" :: "r"(s), "l"(g));
}
#define CP_COMMIT() asm volatile("cp.async.commit_group;" ::: "memory")
#define CP_WAIT1()  asm volatile("cp.async.wait_group 1;" ::: "memory")
#define CP_WAIT0()  asm volatile("cp.async.wait_group 0;" ::: "memory")

__device__ __forceinline__ void ldsm_x4(uint32_t& r0, uint32_t& r1,
                                        uint32_t& r2, uint32_t& r3,
                                        uint32_t addr) {
    asm volatile("ldmatrix.sync.aligned.m8n8.x4.shared.b16 {%0,%1,%2,%3}, [%4];"
                 : "=r"(r0), "=r"(r1), "=r"(r2), "=r"(r3) : "r"(addr));
}
__device__ __forceinline__ void mma16816(float* d, const uint32_t* a,
                                         uint32_t b0, uint32_t b1) {
    asm volatile("mma.sync.aligned.m16n8k16.row.col.f32.bf16.bf16.f32 "
                 "{%0,%1,%2,%3}, {%4,%5,%6,%7}, {%8,%9}, {%0,%1,%2,%3};"
                 : "+f"(d[0]), "+f"(d[1]), "+f"(d[2]), "+f"(d[3])
                 : "r"(a[0]), "r"(a[1]), "r"(a[2]), "r"(a[3]),
                   "r"(b0), "r"(b1));
}

// ---------------- conversion kernels ----------------
__global__ void cvt_x(const float* __restrict__ x) {
    size_t i = (size_t)blockIdx.x * blockDim.x + threadIdx.x;
    if (i < (size_t)B_DIM * S_DIM * I_DIM) {
        float v = x[i];
        __nv_bfloat16 h = __float2bfloat16(v);
        g_xhi[i] = h;
        g_xlo[i] = __float2bfloat16(v - __bfloat162float(h));
    }
}
__global__ void cvt_w(const float* __restrict__ Wf, const float* __restrict__ Wo,
                      const float* __restrict__ Wc) {
    size_t i = (size_t)blockIdx.x * blockDim.x + threadIdx.x;
    if (i < (size_t)3 * H_DIM * I_DIM) {
        int g = (int)(i / (H_DIM * I_DIM));
        size_t rem = i - (size_t)g * H_DIM * I_DIM;
        int h = (int)(rem >> 10), k = (int)(rem & 1023);
        const float* W = (g == 0) ? Wf : (g == 1 ? Wo : Wc);
        float v = W[(size_t)h * KW + k];
        __nv_bfloat16 hh = __float2bfloat16(v);
        g_whi[i] = hh;
        g_wlo[i] = __float2bfloat16(v - __bfloat162float(hh));
    }
}

// ---------------- Phase 1: mma.sync bf16 GEMM (3-term hi/lo), proven ----------------
#define APAD 40
#define ALO_OFF 5120
#define BHI_OFF 10240
#define BLO_OFF 15360
#define STG_ELEMS 20480
#define GSMEM_BYTES (2 * STG_ELEMS * 2)

extern __shared__ __nv_bfloat16 g_sm[];

__global__ __launch_bounds__(256, 1)
void mma_gemm(const float* __restrict__ bf, const float* __restrict__ bo,
              const float* __restrict__ bc) {
    uint32_t sbase = smem_u32(g_sm);
    const int tid = threadIdx.x, lane = tid & 31, warp = tid >> 5;
    const int wm = warp & 1, wn = warp >> 1;
    const int g  = blockIdx.x >> 3;
    const int h0 = (blockIdx.x & 7) * 128;
    const int rowBase = blockIdx.y * 128;
    const size_t aG = (size_t)rowBase * 1024;
    const size_t bG = ((size_t)g * 1024 + h0) * 1024;

    auto loadStage = [&](int st, int kt) {
        uint32_t sb = sbase + st * (STG_ELEMS * 2);
        for (int i = tid; i < 512; i += 256) {
            int r = i >> 2, c = i & 3;
            uint32_t off = (uint32_t)(r * APAD + c * 8) * 2;
            size_t src = (size_t)r * 1024 + kt + c * 8;
            cpasync16(sb + off,               g_xhi + aG + src);
            cpasync16(sb + ALO_OFF * 2 + off, g_xlo + aG + src);
            cpasync16(sb + BHI_OFF * 2 + off, g_whi + bG + src);
            cpasync16(sb + BLO_OFF * 2 + off, g_wlo + bG + src);
        }
    };

    float acc[4][4][4];
#pragma unroll
    for (int mi = 0; mi < 4; mi++)
#pragma unroll
        for (int ni = 0; ni < 4; ni++)
#pragma unroll
            for (int u = 0; u < 4; u++) acc[mi][ni][u] = 0.f;

    loadStage(0, 0);  CP_COMMIT();
    loadStage(1, 32); CP_COMMIT();

    const int aRow = wm * 64 + (lane & 15);
    const int aColB = (lane >> 4) * 16;
    const int bRow = wn * 32 + (lane & 7) + ((lane >> 4) << 3);
    const int bColB = ((lane >> 3) & 1) * 16;

    for (int kt = 0; kt < 32; kt++) {
        CP_WAIT1();
        __syncthreads();
        uint32_t sb = sbase + (kt & 1) * (STG_ELEMS * 2);
#pragma unroll
        for (int kk = 0; kk < 2; kk++) {
            uint32_t ahi[4][4], alo[4][4];
#pragma unroll
            for (int mi = 0; mi < 4; mi++) {
                uint32_t ad = sb + (uint32_t)((aRow + mi * 16) * APAD) * 2
                            + kk * 32 + aColB;
                ldsm_x4(ahi[mi][0], ahi[mi][1], ahi[mi][2], ahi[mi][3], ad);
                ldsm_x4(alo[mi][0], alo[mi][1], alo[mi][2], alo[mi][3],
                        ad + ALO_OFF * 2);
            }
            uint32_t bhi[4][2], blo[4][2];
#pragma unroll
            for (int nh = 0; nh < 2; nh++) {
                uint32_t bd = sb + BHI_OFF * 2
                            + (uint32_t)((bRow + nh * 16) * APAD) * 2
                            + kk * 32 + bColB;
                uint32_t r0, r1, r2, r3;
                ldsm_x4(r0, r1, r2, r3, bd);
                bhi[nh * 2][0] = r0; bhi[nh * 2][1] = r1;
                bhi[nh * 2 + 1][0] = r2; bhi[nh * 2 + 1][1] = r3;
                ldsm_x4(r0, r1, r2, r3, bd + (BLO_OFF - BHI_OFF) * 2);
                blo[nh * 2][0] = r0; blo[nh * 2][1] = r1;
                blo[nh * 2 + 1][0] = r2; blo[nh * 2 + 1][1] = r3;
            }
#pragma unroll
            for (int mi = 0; mi < 4; mi++)
#pragma unroll
                for (int ni = 0; ni < 4; ni++) {
                    mma16816(acc[mi][ni], ahi[mi], bhi[ni][0], bhi[ni][1]);
                    mma16816(acc[mi][ni], ahi[mi], blo[ni][0], blo[ni][1]);
                    mma16816(acc[mi][ni], alo[mi], bhi[ni][0], bhi[ni][1]);
                }
        }
        __syncthreads();
        if (kt + 2 < 32) loadStage(kt & 1, (kt + 2) * 32);
        CP_COMMIT();
    }

    const float* bias = (g == 0) ? bf : (g == 1 ? bo : bc);
    const int b    = rowBase >> 10;
    const int tLoc = rowBase & 1023;
#pragma unroll
    for (int ni = 0; ni < 4; ni++) {
        int h = h0 + wn * 32 + ni * 8 + (lane & 3) * 2;
        float bx = __ldg(&bias[h]), by = __ldg(&bias[h + 1]);
#pragma unroll
        for (int mi = 0; mi < 4; mi++) {
            int t0 = tLoc + wm * 64 + mi * 16 + (lane >> 2);
            float2 v0 = make_float2(acc[mi][ni][0] + bx, acc[mi][ni][1] + by);
            float2 v1 = make_float2(acc[mi][ni][2] + bx, acc[mi][ni][3] + by);
            *(float2*)&g_G[(((size_t)g * S_DIM + t0) * B_DIM + b) * H_DIM + h] = v0;
            *(float2*)&g_G[(((size_t)g * S_DIM + t0 + 8) * B_DIM + b) * H_DIM + h] = v1;
        }
    }
}

// ---------------- init h0 -> bf16 hi/lo [b][h] ----------------
__global__ void init_hb(const float* __restrict__ h0) {
    int i = blockIdx.x * blockDim.x + threadIdx.x;
    if (i < B_DIM * H_DIM) {
        float v = h0[i];
        __nv_bfloat16 hh = __float2bfloat16(v);
        g_hbhi[0][i] = hh;
        g_hblo[0][i] = __float2bfloat16(v - __bfloat162float(hh));
    }
}

// ---------------- Phase 2: persistent recurrence (tensor dot, pipelined) ----------------
#define NB_CTA 128
#define CPB    8
#define NTH    256
// smem byte offsets
#define SW_HI   0u
#define SW_LO   66048u          // 32 rows * 2064 B
#define SH_BASE 132096u         // 2 buffers x (hi 16896 + lo 16896)
#define HBUFSZ  33792u
#define HLO_OFF 16896u
#define PBUF_B  132096u         // alias over h buffers (dead at partials time)
#define CSM_B   199680u
#define TBUF_B  200704u
#define RSMEM_BYTES 201856u
#define WSTRB   2064            // sW row stride bytes (1032 bf16)
#define HSTRB   528             // sH quarter row stride bytes (264 bf16)
#define PSTR    34              // pbuf row stride floats

__device__ __forceinline__ void gridSync(unsigned nb) {
    __syncthreads();
    if (threadIdx.x == 0) {
        __threadfence();
        unsigned gen = *(volatile unsigned*)&g_barGen;
        if (atomicAdd(&g_barCount, 1u) == nb - 1u) {
            *(volatile unsigned*)&g_barCount = 0u;
            __threadfence();
            *(volatile unsigned*)&g_barGen = gen + 1u;
        } else {
            while (*(volatile unsigned*)&g_barGen == gen) { __nanosleep(20); }
        }
        __threadfence();
    }
    __syncthreads();
}
__device__ __forceinline__ float sigm_f(float x) {
    return __fdividef(1.f, 1.f + __expf(-x));
}
__device__ __forceinline__ float tanh_f(float x) {
    return 1.f - __fdividef(2.f, 1.f + __expf(2.f * x));
}

extern __shared__ char r_sm[];

__global__ __launch_bounds__(NTH, 1)
void lstm_recurrent(const float* __restrict__ Wf, const float* __restrict__ Wo,
                    const float* __restrict__ Wc, const float* __restrict__ c0,
                    float* __restrict__ out, int out_size) {
    const uint32_t sA = smem_u32(r_sm);
    float* csm  = (float*)(r_sm + CSM_B);     // [cc*32 + bb]
    float* tbuf = (float*)(r_sm + TBUF_B);    // [bb*9 + cc]
    float* pbuf = (float*)(r_sm + PBUF_B);    // [w][row(34)][batch]

    const int tid  = threadIdx.x;
    const int bid  = blockIdx.x;
    const int c0col = bid * CPB;
    const int lane = tid & 31;
    const int w    = tid >> 5;                // 8 warps
    const unsigned nb = gridDim.x;

    // ---- one-time: recurrent weights fp32 -> bf16 hi/lo into smem ----
    for (int i = tid; i < 24 * 1024; i += NTH) {
        int row = i >> 10, k = i & 1023;
        int gg = row >> 3, cc = row & 7;
        const float* Wsel = (gg == 0) ? Wf : (gg == 1 ? Wo : Wc);
        float v = Wsel[(size_t)(c0col + cc) * KW + I_DIM + k];
        __nv_bfloat16 hh = __float2bfloat16(v);
        __nv_bfloat16 hl = __float2bfloat16(v - __bfloat162float(hh));
        *(__nv_bfloat16*)(r_sm + SW_HI + row * WSTRB + k * 2) = hh;
        *(__nv_bfloat16*)(r_sm + SW_LO + row * WSTRB + k * 2) = hl;
    }
    for (int i = tid; i < 8 * (WSTRB / 4); i += NTH) {
        int row = 24 + i / (WSTRB / 4), wd = i % (WSTRB / 4);
        *(uint32_t*)(r_sm + SW_HI + row * WSTRB + wd * 4) = 0u;
        *(uint32_t*)(r_sm + SW_LO + row * WSTRB + wd * 4) = 0u;
    }
    for (int i = tid; i < B_DIM * CPB; i += NTH) {
        int cc = i >> 5, bb = i & 31;
        csm[cc * 32 + bb] = c0[bb * H_DIM + c0col + cc];
    }
    __syncthreads();

    const bool wantTail = (out_size >= (B_DIM * S_DIM * H_DIM + 2 * B_DIM * H_DIM));

    // ldmatrix lane addressing (form copied from passing R11)
    const int aRB = (lane & 15) * WSTRB + ((lane >> 4) << 4);
    const int bRB = ((lane & 7) + ((lane >> 4) << 3)) * HSTRB
                  + (((lane >> 3) & 1) << 4);

    for (int t = 0; t < S_DIM; t++) {
        const int ep = t & 1, epn = ep ^ 1;
        const __nv_bfloat16* hhiG = g_hbhi[ep];
        const __nv_bfloat16* hloG = g_hblo[ep];

        // stage one K-quarter (256 k) of h hi/lo into buffer `buf`
        // 32 rows x 256 bf16 per plane = 1024 cpasync16 per plane
        auto stageQ = [&](int q, int buf) {
            const uint32_t dst = sA + SH_BASE + (uint32_t)buf * HBUFSZ;
            for (int i = tid; i < 1024; i += NTH) {
                int row = i >> 5, c = i & 31;
                size_t gsrc = (size_t)row * 1024 + q * 256 + c * 8;
                uint32_t o = (uint32_t)(row * HSTRB + c * 16);
                cpasync16(dst + o,           hhiG + gsrc);
                cpasync16(dst + HLO_OFF + o, hloG + gsrc);
            }
        };

        // prefetch x-part pre-activations (warp -> cc, lane -> bb)
        float gxr0, gxr1, gxr2;
        {
            size_t ofs = ((size_t)t * B_DIM + lane) * H_DIM + c0col + w;
            const size_t GSTR = (size_t)S_DIM * B_DIM * H_DIM;
            gxr0 = __ldg(&g_G[ofs]);
            gxr1 = __ldg(&g_G[GSTR + ofs]);
            gxr2 = __ldg(&g_G[2 * GSTR + ofs]);
        }

        float acc[2][4][4];
#pragma unroll
        for (int mi = 0; mi < 2; mi++)
#pragma unroll
            for (int ni = 0; ni < 4; ni++)
#pragma unroll
                for (int u = 0; u < 4; u++) acc[mi][ni][u] = 0.f;

        stageQ(0, 0); CP_COMMIT();

#pragma unroll
        for (int q = 0; q < 4; q++) {
            if (q < 3) { stageQ(q + 1, (q + 1) & 1); CP_COMMIT(); CP_WAIT1(); }
            else       { CP_WAIT0(); }
            __syncthreads();

            const uint32_t hb = sA + SH_BASE + (uint32_t)(q & 1) * HBUFSZ;
#pragma unroll
            for (int kk = 0; kk < 2; kk++) {
                const uint32_t colWb = (uint32_t)(q * 16 + w * 2 + kk) * 32;
                const uint32_t colHb = (uint32_t)(w * 2 + kk) * 32;
                uint32_t whi[2][4], wlo[2][4];
#pragma unroll
                for (int mi = 0; mi < 2; mi++) {
                    uint32_t ad = sA + SW_HI + (uint32_t)(mi * 16 * WSTRB)
                                + aRB + colWb;
                    ldsm_x4(whi[mi][0], whi[mi][1], whi[mi][2], whi[mi][3], ad);
                    ldsm_x4(wlo[mi][0], wlo[mi][1], wlo[mi][2], wlo[mi][3],
                            ad + (SW_LO - SW_HI));
                }
                uint32_t hhi[4][2], hlo[4][2];
#pragma unroll
                for (int nbk = 0; nbk < 2; nbk++) {
                    uint32_t bd = hb + (uint32_t)(nbk * 16 * HSTRB) + bRB + colHb;
                    uint32_t r0, r1, r2, r3;
                    ldsm_x4(r0, r1, r2, r3, bd);
                    hhi[nbk * 2][0] = r0; hhi[nbk * 2][1] = r1;
                    hhi[nbk * 2 + 1][0] = r2; hhi[nbk * 2 + 1][1] = r3;
                    ldsm_x4(r0, r1, r2, r3, bd + HLO_OFF);
                    hlo[nbk * 2][0] = r0; hlo[nbk * 2][1] = r1;
                    hlo[nbk * 2 + 1][0] = r2; hlo[nbk * 2 + 1][1] = r3;
                }
#pragma unroll
                for (int mi = 0; mi < 2; mi++)
#pragma unroll
                    for (int ni = 0; ni < 4; ni++)
                        mma16816(acc[mi][ni], whi[mi], hhi[ni][0], hhi[ni][1]);
#pragma unroll
                for (int mi = 0; mi < 2; mi++)
#pragma unroll
                    for (int ni = 0; ni < 4; ni++)
                        mma16816(acc[mi][ni], whi[mi], hlo[ni][0], hlo[ni][1]);
#pragma unroll
                for (int mi = 0; mi < 2; mi++)
#pragma unroll
                    for (int ni = 0; ni < 4; ni++)
                        mma16816(acc[mi][ni], wlo[mi], hhi[ni][0], hhi[ni][1]);
            }
            __syncthreads();   // buffer reads done before next overwrite
        }

        // ---- partials to smem: pbuf[w][gatecol][batch] ----
#pragma unroll
        for (int mi = 0; mi < 2; mi++) {
            int row0 = mi * 16 + (lane >> 2);
#pragma unroll
            for (int ni = 0; ni < 4; ni++) {
                int col0 = ni * 8 + (lane & 3) * 2;
                float* pb = pbuf + w * (32 * PSTR);
                *(float2*)&pb[row0 * PSTR + col0] =
                    make_float2(acc[mi][ni][0], acc[mi][ni][1]);
                *(float2*)&pb[(row0 + 8) * PSTR + col0] =
                    make_float2(acc[mi][ni][2], acc[mi][ni][3]);
            }
        }
        __syncthreads();

        // ---- reduce 8 partials + gate math (warp = cc, lane = bb) ----
        {
            const int cc = w, bb = lane;
            float pre0 = gxr0, pre1 = gxr1, pre2 = gxr2;
#pragma unroll
            for (int u = 0; u < 8; u++) {
                const float* pb = pbuf + u * (32 * PSTR) + bb;
                pre0 += pb[(cc)      * PSTR];
                pre1 += pb[(8 + cc)  * PSTR];
                pre2 += pb[(16 + cc) * PSTR];
            }
            float f  = sigm_f(pre0);
            float o  = sigm_f(pre1);
            float ch = tanh_f(pre2);
            float cold = csm[cc * 32 + bb];
            float cn = f * (cold - ch) + ch;
            float hn = o * tanh_f(cn);
            csm[cc * 32 + bb] = cn;
            tbuf[bb * 9 + cc] = hn;

            int colg = c0col + cc;
            out[((size_t)bb * S_DIM + t) * H_DIM + colg] = hn;
            if (t == S_DIM - 1 && wantTail) {
                size_t base2 = (size_t)B_DIM * S_DIM * H_DIM;
                out[base2 + (size_t)bb * H_DIM + colg] = hn;
                out[base2 + (size_t)B_DIM * H_DIM + (size_t)bb * H_DIM + colg] = cn;
            }
        }
        __syncthreads();

        // ---- h -> bf16 hi/lo, coalesced store to next epoch ----
        {
            int bb = tid >> 3, cc = tid & 7;
            float v = tbuf[bb * 9 + cc];
            __nv_bfloat16 hh = __float2bfloat16(v);
            __nv_bfloat16 hl = __float2bfloat16(v - __bfloat162float(hh));
            unsigned short uh = *(unsigned short*)&hh;
            unsigned short ul = *(unsigned short*)&hl;
            size_t go = (size_t)bb * H_DIM + c0col + cc;
            asm volatile("st.global.cg.u16 [%0], %1;"
                         :: "l"(&g_hbhi[epn][go]), "h"(uh) : "memory");
            asm volatile("st.global.cg.u16 [%0], %1;"
                         :: "l"(&g_hblo[epn][go]), "h"(ul) : "memory");
        }

        if (t < S_DIM - 1) gridSync(nb);
    }
}

// ---------------- launch ----------------
extern "C" void kernel_launch(void* const* d_in, const int* in_sizes, int n_in,
                              void* d_out, int out_size) {
    const float* x  = (const float*)d_in[0];
    const float* h0 = (const float*)d_in[1];
    const float* c0 = (const float*)d_in[2];
    const float* Wf = (const float*)d_in[3];
    const float* bf = (const float*)d_in[4];
    const float* Wo = (const float*)d_in[5];
    const float* bo = (const float*)d_in[6];
    const float* Wc = (const float*)d_in[7];
    const float* bc = (const float*)d_in[8];
    float* out = (float*)d_out;

    cudaFuncSetAttribute(mma_gemm,
                         cudaFuncAttributeMaxDynamicSharedMemorySize, GSMEM_BYTES);
    cudaFuncSetAttribute(lstm_recurrent,
                         cudaFuncAttributeMaxDynamicSharedMemorySize, RSMEM_BYTES);

    cvt_x<<<(B_DIM * S_DIM * I_DIM + 255) / 256, 256>>>(x);
    cvt_w<<<(3 * H_DIM * I_DIM + 255) / 256, 256>>>(Wf, Wo, Wc);
    mma_gemm<<<dim3(24, 256), 256, GSMEM_BYTES>>>(bf, bo, bc);
    init_hb<<<(B_DIM * H_DIM + 255) / 256, 256>>>(h0);
    lstm_recurrent<<<NB_CTA, NTH, RSMEM_BYTES>>>(Wf, Wo, Wc, c0, out, out_size);
}